// round 5
// baseline (speedup 1.0000x reference)
#include <cuda_runtime.h>

// Problem constants (fixed by the reference)
#define T   12
#define N   10000
#define E   100000
#define CIN 16
#define CE  8
#define HID 32
#define TN  (T*N)

// ---------------- scratch (static __device__, no allocation) ----------------
__device__ float g_h  [TN*HID];   // layer-0 output [T,N,32]   15.4MB
__device__ float g_ea [N*CE];     // per-dst aggregated edge attrs (shared by layers)
__device__ int   g_deg [N];       // in-degree (by dst)
__device__ int   g_rowptr[N + 1]; // CSR row offsets (by dst)
__device__ int   g_cursor[N];     // fill cursors
__device__ int   g_col [E];       // CSR: src node of edge
__device__ int   g_eid [E];       // CSR: original edge id (for edge_attr)
__device__ float g_val [E];       // CSR: norm value

// ---------------- prologue kernels ----------------
__global__ void k_zero_deg() {
    int i = blockIdx.x * blockDim.x + threadIdx.x;
    if (i < N) g_deg[i] = 0;
}
__global__ void k_deg(const int* __restrict__ ei) {
    int e = blockIdx.x * blockDim.x + threadIdx.x;
    if (e < E) atomicAdd(&g_deg[ei[E + e]], 1);
}
// Single-block exclusive scan over g_deg -> g_rowptr / g_cursor. N=10000, 1024 thr.
__global__ void k_scan() {
    __shared__ int sp[1024];
    int tid = threadIdx.x;
    const int chunk = (N + 1023) / 1024;           // 10
    int beg = tid * chunk, end = min(beg + chunk, N);
    int s = 0;
    for (int i = beg; i < end; i++) s += g_deg[i];
    sp[tid] = s;
    __syncthreads();
    for (int off = 1; off < 1024; off <<= 1) {
        int v = (tid >= off) ? sp[tid - off] : 0;
        __syncthreads();
        sp[tid] += v;
        __syncthreads();
    }
    int run = sp[tid] - s;                          // exclusive prefix of this chunk
    for (int i = beg; i < end; i++) {
        g_rowptr[i] = run;
        g_cursor[i] = run;
        run += g_deg[i];
    }
    if (tid == 1023) g_rowptr[N] = run;             // == E
}
// CSR fill with norm computed inline (deg is final here; scan doesn't modify it)
__global__ void k_fill(const int* __restrict__ ei) {
    int e = blockIdx.x * blockDim.x + threadIdx.x;
    if (e < E) {
        int s = ei[e], d = ei[E + e];
        int pos = atomicAdd(&g_cursor[d], 1);
        float ds = (float)max(g_deg[s], 1);
        float dd = (float)max(g_deg[d], 1);
        g_col[pos] = s;
        g_eid[pos] = e;
        g_val[pos] = rsqrtf(ds * dd);
    }
}

// ---------------- edge-attr aggregate (ONCE, shared by both layers) ----------
// g_ea[d, c] = sum over edges e into d of norm_e * edge_attr[e, c]   (c < 8)
// Warp per node: 4 lane-groups of 8 split the edge list, then shfl-reduce.
__global__ void k_eaagg(const float* __restrict__ eattr) {
    int d = (blockIdx.x * blockDim.x + threadIdx.x) >> 5;
    if (d >= N) return;
    int lane = threadIdx.x & 31;
    int c  = lane & 7;
    int gi = lane >> 3;                     // 0..3: edge-list stripe
    int beg = g_rowptr[d], end = g_rowptr[d + 1];
    float acc = 0.f;
    for (int j = beg + gi; j < end; j += 4) {
        int e = g_eid[j];
        float nv = g_val[j];
        acc = fmaf(nv, __ldg(eattr + (size_t)e * CE + c), acc);
    }
    acc += __shfl_xor_sync(0xffffffffu, acc, 8);
    acc += __shfl_xor_sync(0xffffffffu, acc, 16);
    if (gi == 0) g_ea[(size_t)d * CE + c] = acc;
}

// ---------------- fused layer: gather (input space) + projection + GRU -------
// Per node d:
//   gxa[t,:] = sum_{edges e into d} norm_e * in[t, src_e, :]         (KX ch)
//   R[t,c] = bg[H+c] + gxa[t]@Wg[0:KX, H+c] + ea[d]@Weg[:, H+c]
//   U[t,c] = bu[c]   + gxa[t]@Wu[0:KX, c]   + ea[d]@Weu[:, c]
//   out[t,d,c] = (1 - sigmoid(R)) * tanh(U)   [+ relu if layer 0]
// Block = 256 thr = 8 warps = 8 nodes. Warp-uniform edge loop (no divergence).
// Gather lane map: tg = lane>>3 owns t in {3tg..3tg+2}; q = lane&7 owns a
// KX/8-channel slice. Proj lane map: lane = output channel.
__device__ __forceinline__ float sigm(float x) { return 1.f / (1.f + expf(-x)); }

template <int KX, bool RELU>
__device__ __forceinline__ void fused_body(const float* __restrict__ in,
                                           const float* __restrict__ Wg,
                                           const float* __restrict__ Weg,
                                           const float* __restrict__ bg,
                                           const float* __restrict__ Wu,
                                           const float* __restrict__ Weu,
                                           const float* __restrict__ bu,
                                           float* __restrict__ out) {
    const int KT = KX + CE;
    __shared__ float sR[(KX + CE) * HID];
    __shared__ float sU[(KX + CE) * HID];
    __shared__ float sx[8 * T * KX];                // per-warp [T][KX] tiles
    int tid = threadIdx.x;
    for (int i = tid; i < KT * HID; i += 256) {
        int k = i >> 5, c = i & 31;
        sR[i] = (k < KX) ? Wg[k * (2 * HID) + HID + c]
                         : Weg[(k - KX) * (2 * HID) + HID + c];
        sU[i] = (k < KX) ? Wu[k * HID + c]
                         : Weu[(k - KX) * HID + c];
    }
    __syncthreads();

    int w = tid >> 5;
    int d = blockIdx.x * 8 + w;
    if (d >= N) return;
    int lane = tid & 31;
    float* mytile = sx + w * (T * KX);

    // ---- gather phase ----
    {
        int tg = lane >> 3;          // 0..3
        int t0 = tg * 3;
        int beg = g_rowptr[d], end = g_rowptr[d + 1];
        if (KX == 16) {
            int cp = (lane & 7) * 2;
            float2 acc[3] = {{0.f,0.f},{0.f,0.f},{0.f,0.f}};
            for (int j = beg; j < end; j++) {
                int s   = g_col[j];   // warp-uniform -> broadcast
                float nv = g_val[j];
                #pragma unroll
                for (int k = 0; k < 3; k++) {
                    float2 v = *reinterpret_cast<const float2*>(
                        in + ((size_t)(t0 + k) * N + s) * KX + cp);
                    acc[k].x = fmaf(nv, v.x, acc[k].x);
                    acc[k].y = fmaf(nv, v.y, acc[k].y);
                }
            }
            #pragma unroll
            for (int k = 0; k < 3; k++)
                *reinterpret_cast<float2*>(mytile + (t0 + k) * KX + cp) = acc[k];
        } else {                      // KX == 32
            int c4 = (lane & 7) * 4;
            float4 acc[3];
            #pragma unroll
            for (int k = 0; k < 3; k++) acc[k] = make_float4(0.f, 0.f, 0.f, 0.f);
            for (int j = beg; j < end; j++) {
                int s   = g_col[j];
                float nv = g_val[j];
                #pragma unroll
                for (int k = 0; k < 3; k++) {
                    float4 v = *reinterpret_cast<const float4*>(
                        in + ((size_t)(t0 + k) * N + s) * KX + c4);
                    acc[k].x = fmaf(nv, v.x, acc[k].x);
                    acc[k].y = fmaf(nv, v.y, acc[k].y);
                    acc[k].z = fmaf(nv, v.z, acc[k].z);
                    acc[k].w = fmaf(nv, v.w, acc[k].w);
                }
            }
            #pragma unroll
            for (int k = 0; k < 3; k++)
                *reinterpret_cast<float4*>(mytile + (t0 + k) * KX + c4) = acc[k];
        }
    }
    __syncwarp();

    // ---- projection + GRU phase (lane = output channel) ----
    int c = lane;
    // t-independent edge-attr + bias term
    float eaR = __ldg(bg + HID + c);
    float eaU = __ldg(bu + c);
    const float* er = g_ea + (size_t)d * CE;
    #pragma unroll
    for (int k = 0; k < CE; k++) {
        float v = er[k];              // warp-uniform
        eaR = fmaf(v, sR[(KX + k) * HID + c], eaR);
        eaU = fmaf(v, sU[(KX + k) * HID + c], eaU);
    }
    for (int t = 0; t < T; t++) {
        float aR = eaR, aU = eaU;
        const float* xt = mytile + t * KX;
        #pragma unroll
        for (int k = 0; k < KX; k++) {
            float v = xt[k];          // broadcast, conflict-free
            aR = fmaf(v, sR[k * HID + c], aR);
            aU = fmaf(v, sU[k * HID + c], aU);
        }
        float v = (1.f - sigm(aR)) * tanhf(aU);
        if (RELU) v = fmaxf(v, 0.f);
        out[((size_t)t * N + d) * HID + c] = v;
    }
}
__global__ void k_layer0(const float* __restrict__ x,
                         const float* __restrict__ Wg, const float* __restrict__ Weg,
                         const float* __restrict__ bg, const float* __restrict__ Wu,
                         const float* __restrict__ Weu, const float* __restrict__ bu) {
    fused_body<CIN, true>(x, Wg, Weg, bg, Wu, Weu, bu, g_h);
}
__global__ void k_layer1(const float* __restrict__ Wg, const float* __restrict__ Weg,
                         const float* __restrict__ bg, const float* __restrict__ Wu,
                         const float* __restrict__ Weu, const float* __restrict__ bu,
                         float* __restrict__ out) {
    fused_body<HID, false>(g_h, Wg, Weg, bg, Wu, Weu, bu, out);
}

// ---------------- launch ----------------
extern "C" void kernel_launch(void* const* d_in, const int* in_sizes, int n_in,
                              void* d_out, int out_size) {
    const float* x    = (const float*)d_in[0];
    const int*   ei   = (const int*)  d_in[1];
    const float* ea   = (const float*)d_in[2];
    const float* Wg0  = (const float*)d_in[3];
    const float* Weg0 = (const float*)d_in[4];
    const float* bg0  = (const float*)d_in[5];
    const float* Wu0  = (const float*)d_in[6];
    const float* Weu0 = (const float*)d_in[7];
    const float* bu0  = (const float*)d_in[8];
    const float* Wg1  = (const float*)d_in[9];
    const float* Weg1 = (const float*)d_in[10];
    const float* bg1  = (const float*)d_in[11];
    const float* Wu1  = (const float*)d_in[12];
    const float* Weu1 = (const float*)d_in[13];
    const float* bu1  = (const float*)d_in[14];
    float* out = (float*)d_out;

    const int warpsGrid = (N * 32 + 255) / 256;   // warp-per-node kernels
    const int nodeGrid  = (N + 7) / 8;            // 8 nodes per block (fused)

    // prologue: degree, CSR(+norm), edge-attr aggregate (shared by both layers)
    k_zero_deg<<<(N + 255) / 256, 256>>>();
    k_deg <<<(E + 255) / 256, 256>>>(ei);
    k_scan<<<1, 1024>>>();
    k_fill<<<(E + 255) / 256, 256>>>(ei);
    k_eaagg<<<warpsGrid, 256>>>(ea);

    // ---- layer 0: fused gather(16ch) + project + GRU + relu -> g_h ----
    k_layer0<<<nodeGrid, 256>>>(x, Wg0, Weg0, bg0, Wu0, Weu0, bu0);

    // ---- layer 1: fused gather(32ch) + project + GRU -> out ----
    k_layer1<<<nodeGrid, 256>>>(Wg1, Weg1, bg1, Wu1, Weu1, bu1, out);
}

// round 7
// speedup vs baseline: 1.5539x; 1.5539x over previous
#include <cuda_runtime.h>

// Problem constants (fixed by the reference)
#define T   12
#define N   10000
#define E   100000
#define CIN 16
#define CE  8
#define HID 32
#define TN  (T*N)

// CSR edge record: one 16B load/store per edge
struct __align__(16) EdgeRec { int col; int eid; float val; float pad; };

// ---------------- scratch (static __device__, no allocation) ----------------
__device__ float   g_h  [TN*HID];   // layer-0 output [T,N,32]   15.4MB
__device__ float   g_ea [N*CE];     // per-dst aggregated edge attrs (layer0 -> layer1)
__device__ int     g_deg [N];       // in-degree (by dst)
__device__ int     g_rowptr[N + 1]; // CSR row offsets (by dst)
__device__ int     g_cursor[N];     // fill cursors
__device__ EdgeRec g_edges[E];      // CSR payload: src, edge-id, norm

// ---------------- prologue kernels ----------------
__global__ void k_zero_deg() {
    int i = blockIdx.x * blockDim.x + threadIdx.x;
    if (i < N) g_deg[i] = 0;
}
__global__ void k_deg(const int* __restrict__ ei) {
    int e = blockIdx.x * blockDim.x + threadIdx.x;
    if (e < E) atomicAdd(&g_deg[ei[E + e]], 1);
}
// Single-block exclusive scan over g_deg -> g_rowptr / g_cursor. N=10000, 1024 thr.
__global__ void k_scan() {
    __shared__ int sp[1024];
    int tid = threadIdx.x;
    const int chunk = (N + 1023) / 1024;           // 10
    int beg = tid * chunk, end = min(beg + chunk, N);
    int s = 0;
    for (int i = beg; i < end; i++) s += g_deg[i];
    sp[tid] = s;
    __syncthreads();
    for (int off = 1; off < 1024; off <<= 1) {
        int v = (tid >= off) ? sp[tid - off] : 0;
        __syncthreads();
        sp[tid] += v;
        __syncthreads();
    }
    int run = sp[tid] - s;                          // exclusive prefix of this chunk
    for (int i = beg; i < end; i++) {
        g_rowptr[i] = run;
        g_cursor[i] = run;
        run += g_deg[i];
    }
    if (tid == 1023) g_rowptr[N] = run;             // == E
}
// CSR fill; 2 edges per thread for ILP (latency-bound kernel).
__global__ void k_fill(const int* __restrict__ ei) {
    int e = blockIdx.x * blockDim.x + threadIdx.x;
    const int half = E / 2;                         // E even
    if (e < half) {
        #pragma unroll
        for (int r = 0; r < 2; r++) {
            int ee = e + r * half;
            int s = ei[ee], d = ei[E + ee];
            int pos = atomicAdd(&g_cursor[d], 1);
            float ds = (float)max(g_deg[s], 1);
            float dd = (float)max(g_deg[d], 1);
            EdgeRec rec;
            rec.col = s; rec.eid = ee; rec.val = rsqrtf(ds * dd); rec.pad = 0.f;
            g_edges[pos] = rec;
        }
    }
}

// ---------------- fused layer: gather (input space) + projection + GRU -------
// Per node d:
//   gxa[t,:] = sum_{edges e into d} norm_e * in[t, src_e, :]         (KX ch)
//   ea[:]    = sum_{edges e into d} norm_e * eattr[e,:]              (8 ch; layer0
//              computes+persists, layer1 reloads)
//   R[t,c] = bg[H+c] + gxa[t]@Wg[0:KX, H+c] + ea@Weg[:, H+c]
//   U[t,c] = bu[c]   + gxa[t]@Wu[0:KX, c]   + ea@Weu[:, c]
//   out[t,d,c] = (1 - sigmoid(R)) * tanh(U)   [+ relu if layer 0]
// Block = 256 thr = 8 warps = 8 nodes. Edge records staged through smem in
// chunks of 32 (coalesced LDG.128) so the per-edge gather loads pipeline with
// high MLP instead of serializing on a uniform L2 load each iteration.
// Gather lane map: tg=lane>>3 -> t in {3tg..3tg+2}; q=lane&7 -> channel slice.
// Tile stored TRANSPOSED [KX][16] so projection reads x[k][t] as LDS.128.
__device__ __forceinline__ float sigm(float x) { return 1.f / (1.f + __expf(-x)); }

template <int KX, bool RELU, bool COMPUTE_EA>
__device__ __forceinline__ void fused_body(const float* __restrict__ in,
                                           const float* __restrict__ eattr,
                                           const float* __restrict__ Wg,
                                           const float* __restrict__ Weg,
                                           const float* __restrict__ bg,
                                           const float* __restrict__ Wu,
                                           const float* __restrict__ Weu,
                                           const float* __restrict__ bu,
                                           float* __restrict__ out) {
    const int KT = KX + CE;
    __shared__ float  sR[(KX + CE) * HID];
    __shared__ float  sU[(KX + CE) * HID];
    __shared__ float  sx[8 * KX * 16];              // per-warp transposed [KX][16]
    __shared__ float  sEA[8 * CE];
    __shared__ float4 sEdge[8 * 32];                // per-warp edge-record stage
    int tid = threadIdx.x;
    for (int i = tid; i < KT * HID; i += 256) {
        int k = i >> 5, c = i & 31;
        sR[i] = (k < KX) ? Wg[k * (2 * HID) + HID + c]
                         : Weg[(k - KX) * (2 * HID) + HID + c];
        sU[i] = (k < KX) ? Wu[k * HID + c]
                         : Weu[(k - KX) * HID + c];
    }
    __syncthreads();

    int w = tid >> 5;
    int d = blockIdx.x * 8 + w;
    if (d >= N) return;
    int lane = tid & 31;
    float*  tile = sx + w * (KX * 16);
    float4* est  = sEdge + w * 32;
    const float4* gedges4 = reinterpret_cast<const float4*>(g_edges);
    int t0 = (lane >> 3) * 3;
    int beg = g_rowptr[d], end = g_rowptr[d + 1];

    // ---- gather phase ----
    if (KX == 16) {
        int cp = (lane & 7) * 2;
        int ec = lane & 7;
        float2 acc[3] = {{0.f,0.f},{0.f,0.f},{0.f,0.f}};
        float eacc = 0.f;
        for (int base = beg; base < end; base += 32) {
            int n = min(32, end - base);
            if (lane < n) est[lane] = __ldg(gedges4 + base + lane);
            __syncwarp();
            for (int j = 0; j < n; j++) {
                float4 rec = est[j];
                int   s  = __float_as_int(rec.x);
                float nv = rec.z;
                if (COMPUTE_EA) {
                    int eid = __float_as_int(rec.y);
                    eacc = fmaf(nv, __ldg(eattr + (size_t)eid * CE + ec), eacc);
                }
                #pragma unroll
                for (int k = 0; k < 3; k++) {
                    float2 v = *reinterpret_cast<const float2*>(
                        in + ((size_t)(t0 + k) * N + s) * KX + cp);
                    acc[k].x = fmaf(nv, v.x, acc[k].x);
                    acc[k].y = fmaf(nv, v.y, acc[k].y);
                }
            }
            __syncwarp();
        }
        #pragma unroll
        for (int k = 0; k < 3; k++) {             // transposed scalar stores
            tile[(cp    ) * 16 + t0 + k] = acc[k].x;
            tile[(cp + 1) * 16 + t0 + k] = acc[k].y;
        }
        if (COMPUTE_EA && lane < CE) {
            sEA[w * CE + lane] = eacc;            // all 4 tg groups computed same
            g_ea[(size_t)d * CE + lane] = eacc;   // persist for layer 1
        }
    } else {                                      // KX == 32
        int c4 = (lane & 7) * 4;
        float4 acc[3];
        #pragma unroll
        for (int k = 0; k < 3; k++) acc[k] = make_float4(0.f, 0.f, 0.f, 0.f);
        for (int base = beg; base < end; base += 32) {
            int n = min(32, end - base);
            if (lane < n) est[lane] = __ldg(gedges4 + base + lane);
            __syncwarp();
            for (int j = 0; j < n; j++) {
                float4 rec = est[j];
                int   s  = __float_as_int(rec.x);
                float nv = rec.z;
                #pragma unroll
                for (int k = 0; k < 3; k++) {
                    float4 v = *reinterpret_cast<const float4*>(
                        in + ((size_t)(t0 + k) * N + s) * KX + c4);
                    acc[k].x = fmaf(nv, v.x, acc[k].x);
                    acc[k].y = fmaf(nv, v.y, acc[k].y);
                    acc[k].z = fmaf(nv, v.z, acc[k].z);
                    acc[k].w = fmaf(nv, v.w, acc[k].w);
                }
            }
            __syncwarp();
        }
        #pragma unroll
        for (int k = 0; k < 3; k++) {
            tile[(c4    ) * 16 + t0 + k] = acc[k].x;
            tile[(c4 + 1) * 16 + t0 + k] = acc[k].y;
            tile[(c4 + 2) * 16 + t0 + k] = acc[k].z;
            tile[(c4 + 3) * 16 + t0 + k] = acc[k].w;
        }
        if (lane < CE)
            sEA[w * CE + lane] = g_ea[(size_t)d * CE + lane];
    }
    __syncwarp();

    // ---- projection + GRU phase (lane = output channel; k-outer, t-inner) ----
    int c = lane;
    float eaR = __ldg(bg + HID + c);
    float eaU = __ldg(bu + c);
    #pragma unroll
    for (int k = 0; k < CE; k++) {
        float v = sEA[w * CE + k];                // broadcast
        eaR = fmaf(v, sR[(KX + k) * HID + c], eaR);
        eaU = fmaf(v, sU[(KX + k) * HID + c], eaU);
    }
    float aR[T], aU[T];
    #pragma unroll
    for (int t = 0; t < T; t++) { aR[t] = eaR; aU[t] = eaU; }

    #pragma unroll 4
    for (int k = 0; k < KX; k++) {
        float wR = sR[k * HID + c];
        float wU = sU[k * HID + c];
        const float* xr = tile + k * 16;
        float xv[T];
        #pragma unroll
        for (int q = 0; q < 3; q++) {             // 3x LDS.128, broadcast
            float4 xq = *reinterpret_cast<const float4*>(xr + q * 4);
            xv[q * 4 + 0] = xq.x; xv[q * 4 + 1] = xq.y;
            xv[q * 4 + 2] = xq.z; xv[q * 4 + 3] = xq.w;
        }
        #pragma unroll
        for (int t = 0; t < T; t++) {
            aR[t] = fmaf(xv[t], wR, aR[t]);
            aU[t] = fmaf(xv[t], wU, aU[t]);
        }
    }
    #pragma unroll
    for (int t = 0; t < T; t++) {
        float v = (1.f - sigm(aR[t])) * tanhf(aU[t]);
        if (RELU) v = fmaxf(v, 0.f);
        out[((size_t)t * N + d) * HID + c] = v;   // coalesced 128B per t
    }
}

__global__ void __launch_bounds__(256)
k_layer0(const float* __restrict__ x, const float* __restrict__ eattr,
         const float* __restrict__ Wg, const float* __restrict__ Weg,
         const float* __restrict__ bg, const float* __restrict__ Wu,
         const float* __restrict__ Weu, const float* __restrict__ bu) {
    fused_body<CIN, true, true>(x, eattr, Wg, Weg, bg, Wu, Weu, bu, g_h);
}
__global__ void __launch_bounds__(256)
k_layer1(const float* __restrict__ Wg, const float* __restrict__ Weg,
         const float* __restrict__ bg, const float* __restrict__ Wu,
         const float* __restrict__ Weu, const float* __restrict__ bu,
         float* __restrict__ out) {
    fused_body<HID, false, false>(g_h, nullptr, Wg, Weg, bg, Wu, Weu, bu, out);
}

// ---------------- launch ----------------
extern "C" void kernel_launch(void* const* d_in, const int* in_sizes, int n_in,
                              void* d_out, int out_size) {
    const float* x    = (const float*)d_in[0];
    const int*   ei   = (const int*)  d_in[1];
    const float* ea   = (const float*)d_in[2];
    const float* Wg0  = (const float*)d_in[3];
    const float* Weg0 = (const float*)d_in[4];
    const float* bg0  = (const float*)d_in[5];
    const float* Wu0  = (const float*)d_in[6];
    const float* Weu0 = (const float*)d_in[7];
    const float* bu0  = (const float*)d_in[8];
    const float* Wg1  = (const float*)d_in[9];
    const float* Weg1 = (const float*)d_in[10];
    const float* bg1  = (const float*)d_in[11];
    const float* Wu1  = (const float*)d_in[12];
    const float* Weu1 = (const float*)d_in[13];
    const float* bu1  = (const float*)d_in[14];
    float* out = (float*)d_out;

    const int nodeGrid = (N + 7) / 8;             // 8 nodes per block (fused)

    // prologue: degree, CSR(+norm) build
    k_zero_deg<<<(N + 255) / 256, 256>>>();
    k_deg <<<(E + 255) / 256, 256>>>(ei);
    k_scan<<<1, 1024>>>();
    k_fill<<<(E / 2 + 255) / 256, 256>>>(ei);

    // ---- layer 0: fused gather(16ch) + edge-attr agg + project + GRU + relu ----
    k_layer0<<<nodeGrid, 256>>>(x, ea, Wg0, Weg0, bg0, Wu0, Weu0, bu0);

    // ---- layer 1: fused gather(32ch) + project + GRU -> out ----
    k_layer1<<<nodeGrid, 256>>>(Wg1, Weg1, bg1, Wu1, Weu1, bu1, out);
}